// round 2
// baseline (speedup 1.0000x reference)
#include <cuda_runtime.h>
#include <cuda_bf16.h>
#include <math.h>

// Problem constants
#define Bq   2
#define Tq   2048
#define Cq   1024
#define Hq   16
#define HDq  64
#define Mq   2048

// Scratch (allocation-free rule: __device__ globals)
__device__ float g_k[Bq * Tq * Cq];   // relu(x @ w1^T + b1)
__device__ float g_v[Bq * Tq * Cq];   // x @ value^T + vb
__device__ float g_y[Bq * Tq * Cq];   // attention output (pre-proj)

// ---------------------------------------------------------------------------
// Dense GEMM: C[M,N] = act(A[M,K] @ W[N,K]^T + bias[N])
// 64x64 block tile, BK=32, 256 threads, 4x4 per-thread microtile.
// ---------------------------------------------------------------------------
template <bool RELU>
__global__ __launch_bounds__(256) void gemm_bias_kernel(
    const float* __restrict__ A, const float* __restrict__ W,
    const float* __restrict__ bias, float* __restrict__ Cmat,
    int Mdim, int Ndim, int Kdim)
{
    const int BM = 64, BN = 64, BK = 32;
    __shared__ float As[BK][BM];
    __shared__ float Bs[BK][BN];

    const int m0 = blockIdx.y * BM;
    const int n0 = blockIdx.x * BN;
    const int tid = threadIdx.x;
    const int tx = tid & 15;        // 0..15 -> 4 cols each
    const int ty = tid >> 4;        // 0..15 -> 4 rows each

    float acc[4][4];
#pragma unroll
    for (int i = 0; i < 4; i++)
#pragma unroll
        for (int j = 0; j < 4; j++) acc[i][j] = 0.f;

    for (int k0 = 0; k0 < Kdim; k0 += BK) {
        // Cooperative loads: 64x32 each, fully coalesced (32 floats per row).
#pragma unroll
        for (int i = 0; i < 8; i++) {
            int flat = tid + i * 256;
            int k = flat & (BK - 1);
            int r = flat / BK;
            As[k][r] = A[(m0 + r) * Kdim + k0 + k];
            Bs[k][r] = W[(n0 + r) * Kdim + k0 + k];
        }
        __syncthreads();

#pragma unroll
        for (int k = 0; k < BK; k++) {
            float a[4], bv[4];
            float4 av = *(const float4*)&As[k][ty * 4];
            float4 bvv = *(const float4*)&Bs[k][tx * 4];
            a[0] = av.x; a[1] = av.y; a[2] = av.z; a[3] = av.w;
            bv[0] = bvv.x; bv[1] = bvv.y; bv[2] = bvv.z; bv[3] = bvv.w;
#pragma unroll
            for (int i = 0; i < 4; i++)
#pragma unroll
                for (int j = 0; j < 4; j++)
                    acc[i][j] += a[i] * bv[j];
        }
        __syncthreads();
    }

    const float4 bq = *(const float4*)&bias[n0 + tx * 4];
    const float bb[4] = {bq.x, bq.y, bq.z, bq.w};
#pragma unroll
    for (int i = 0; i < 4; i++) {
        float4 o;
        float v0 = acc[i][0] + bb[0];
        float v1 = acc[i][1] + bb[1];
        float v2 = acc[i][2] + bb[2];
        float v3 = acc[i][3] + bb[3];
        if (RELU) {
            v0 = fmaxf(v0, 0.f); v1 = fmaxf(v1, 0.f);
            v2 = fmaxf(v2, 0.f); v3 = fmaxf(v3, 0.f);
        }
        o.x = v0; o.y = v1; o.z = v2; o.w = v3;
        *(float4*)&Cmat[(m0 + ty * 4 + i) * Ndim + n0 + tx * 4] = o;
    }
}

// ---------------------------------------------------------------------------
// Fused synthesizer attention:
//   per block: (b, h, 16 query rows)
//   1) load K rows (16x64) to SMEM
//   2) scores S[16 x Lc] = K @ w2[h] + b2 into SMEM (causal Lc = t0+16)
//   3) exact softmax per row in SMEM (cols 0..t)
//   4) out[16x64] = P @ V, streamed from global V
// SMEM: 16*2048 (scores) + 16*64 (K) floats = 132 KB dynamic.
// ---------------------------------------------------------------------------
__global__ __launch_bounds__(256) void attn_kernel(
    const float* __restrict__ gk, const float* __restrict__ gv,
    const float* __restrict__ w2, const float* __restrict__ b2,
    float* __restrict__ gy)
{
    extern __shared__ float sm[];
    float* ps = sm;                  // [16][2048]
    float* ks = sm + 16 * 2048;      // [16][64]

    const int t0 = blockIdx.x * 16;
    const int h  = blockIdx.y;
    const int b  = blockIdx.z;
    const int tid = threadIdx.x;
    const int Lc = t0 + 16;          // columns needed (causal)

    // ---- load K rows ----
#pragma unroll
    for (int i = 0; i < 4; i++) {
        int flat = tid + i * 256;
        int d = flat & 63, r = flat >> 6;
        ks[r * 64 + d] = gk[(b * Tq + t0 + r) * Cq + h * HDq + d];
    }
    __syncthreads();

    // ---- scores: each thread owns one column m per 256-chunk ----
    const float* w2h = w2 + h * HDq * Mq;
    for (int mb = 0; mb < Lc; mb += 256) {
        int m = mb + tid;
        if (m < Lc) {
            float bias = __ldg(&b2[m]);
            float acc[16];
#pragma unroll
            for (int r = 0; r < 16; r++) acc[r] = bias;
#pragma unroll 4
            for (int d4 = 0; d4 < 16; d4++) {
                float w0 = w2h[(d4 * 4 + 0) * Mq + m];
                float w1 = w2h[(d4 * 4 + 1) * Mq + m];
                float w2v = w2h[(d4 * 4 + 2) * Mq + m];
                float w3 = w2h[(d4 * 4 + 3) * Mq + m];
#pragma unroll
                for (int r = 0; r < 16; r++) {
                    float4 kv = *(const float4*)&ks[r * 64 + d4 * 4];
                    acc[r] += kv.x * w0;
                    acc[r] += kv.y * w1;
                    acc[r] += kv.z * w2v;
                    acc[r] += kv.w * w3;
                }
            }
#pragma unroll
            for (int r = 0; r < 16; r++)
                ps[r * 2048 + m] = acc[r];   // masked tail (m>t) never read
        }
    }
    __syncthreads();

    // ---- softmax per row (exact; valid cols 0..t) ----
    {
        const int wid = tid >> 5, lane = tid & 31;
        for (int r = wid; r < 16; r += 8) {
            const int n = t0 + r + 1;
            float* row = ps + r * 2048;
            float mx = -1e30f;
            for (int m = lane; m < n; m += 32) mx = fmaxf(mx, row[m]);
#pragma unroll
            for (int off = 16; off; off >>= 1)
                mx = fmaxf(mx, __shfl_xor_sync(0xffffffffu, mx, off));
            float sum = 0.f;
            for (int m = lane; m < n; m += 32) {
                float e = __expf(row[m] - mx);
                row[m] = e;
                sum += e;
            }
#pragma unroll
            for (int off = 16; off; off >>= 1)
                sum += __shfl_xor_sync(0xffffffffu, sum, off);
            float inv = 1.f / sum;
            for (int m = lane; m < n; m += 32) row[m] *= inv;
        }
    }
    __syncthreads();

    // ---- P @ V: thread = (row r, 4 cols), stream V rows via float4 ----
    {
        const int r = tid >> 4;           // 0..15
        const int c4 = (tid & 15) * 4;    // 0..60
        const int t = t0 + r;
        const int n = t + 1;
        const float* prow = ps + r * 2048;
        const float* vb = gv + b * Tq * Cq + h * HDq + c4;
        float o0 = 0.f, o1 = 0.f, o2 = 0.f, o3 = 0.f;
#pragma unroll 4
        for (int l = 0; l < n; l++) {
            float p = prow[l];
            float4 vv = *(const float4*)&vb[l * Cq];
            o0 += p * vv.x; o1 += p * vv.y; o2 += p * vv.z; o3 += p * vv.w;
        }
        float4 o; o.x = o0; o.y = o1; o.z = o2; o.w = o3;
        *(float4*)&gy[(b * Tq + t) * Cq + h * HDq + c4] = o;
    }
}

// ---------------------------------------------------------------------------
extern "C" void kernel_launch(void* const* d_in, const int* in_sizes, int n_in,
                              void* d_out, int out_size)
{
    const float* x       = (const float*)d_in[0];
    const float* w1_w    = (const float*)d_in[1];
    const float* w1_b    = (const float*)d_in[2];
    const float* w2      = (const float*)d_in[3];
    const float* b2      = (const float*)d_in[4];
    const float* value_w = (const float*)d_in[5];
    const float* value_b = (const float*)d_in[6];
    const float* proj_w  = (const float*)d_in[7];
    const float* proj_b  = (const float*)d_in[8];
    float* out = (float*)d_out;

    float *pk, *pv, *py;
    cudaGetSymbolAddress((void**)&pk, g_k);
    cudaGetSymbolAddress((void**)&pv, g_v);
    cudaGetSymbolAddress((void**)&py, g_y);

    const int SMEM_ATTN = (16 * 2048 + 16 * 64) * (int)sizeof(float);  // 132 KB
    cudaFuncSetAttribute(attn_kernel,
                         cudaFuncAttributeMaxDynamicSharedMemorySize, SMEM_ATTN);

    const int Mrows = Bq * Tq;  // 4096
    dim3 gemm_grid(Cq / 64, Mrows / 64);

    // k = relu(x @ w1^T + b1)
    gemm_bias_kernel<true><<<gemm_grid, 256>>>(x, w1_w, w1_b, pk, Mrows, Cq, Cq);
    // v = x @ value^T + vb
    gemm_bias_kernel<false><<<gemm_grid, 256>>>(x, value_w, value_b, pv, Mrows, Cq, Cq);
    // fused scores + softmax + PV
    dim3 agrid(Tq / 16, Hq, Bq);
    attn_kernel<<<agrid, 256, SMEM_ATTN>>>(pk, pv, w2, b2, py);
    // out = y @ proj^T + pb
    gemm_bias_kernel<false><<<gemm_grid, 256>>>(py, proj_w, proj_b, out, Mrows, Cq, Cq);
}